// round 1
// baseline (speedup 1.0000x reference)
#include <cuda_runtime.h>
#include <math.h>

// Problem constants (B=4, T=2048, C=1024, H=16, D=64)
#define Bn   4
#define Tn   2048
#define Cc   1024
#define NH   16
#define HD   64
#define MTOT (Bn * Tn)          // 8192 rows

// Scratch (device globals: allocation is forbidden)
__device__ float g_qkv[(size_t)MTOT * 3 * Cc];  // (B*T, 3C) = x @ w_attn^T
__device__ float g_att[(size_t)MTOT * Cc];      // (B*T, C)  attention output

// ---------------------------------------------------------------------------
// SGEMM: C[M,N] = A[M,K] @ B[N,K]^T   (A,B,C row-major; M%128==0, N%128==0, K%8==0)
// 128x128 tile, BK=8, 256 threads, 8x8 per thread.
// ---------------------------------------------------------------------------
__global__ __launch_bounds__(256) void gemm_nt_kernel(
    const float* __restrict__ A, const float* __restrict__ B,
    float* __restrict__ C, int M, int N, int K)
{
    const int BM = 128, BN = 128, BK = 8;
    __shared__ float As[BK][BM];
    __shared__ float Bs[BK][BN];

    const int tid = threadIdx.x;
    const int m0  = blockIdx.y * BM;
    const int n0  = blockIdx.x * BN;

    const int lrow = tid >> 1;            // 0..127
    const int lc4  = (tid & 1) * 4;       // 0 or 4

    const float* Ag = A + (size_t)(m0 + lrow) * K + lc4;
    const float* Bg = B + (size_t)(n0 + lrow) * K + lc4;

    const int ty = tid >> 4;              // 0..15 -> 8 M-rows each
    const int tx = tid & 15;              // 0..15 -> 8 N-cols each

    float acc[8][8];
    #pragma unroll
    for (int i = 0; i < 8; i++)
        #pragma unroll
        for (int j = 0; j < 8; j++) acc[i][j] = 0.0f;

    for (int k0 = 0; k0 < K; k0 += BK) {
        float4 av = *(const float4*)(Ag + k0);
        float4 bv = *(const float4*)(Bg + k0);
        As[lc4 + 0][lrow] = av.x; As[lc4 + 1][lrow] = av.y;
        As[lc4 + 2][lrow] = av.z; As[lc4 + 3][lrow] = av.w;
        Bs[lc4 + 0][lrow] = bv.x; Bs[lc4 + 1][lrow] = bv.y;
        Bs[lc4 + 2][lrow] = bv.z; Bs[lc4 + 3][lrow] = bv.w;
        __syncthreads();

        #pragma unroll
        for (int kk = 0; kk < BK; kk++) {
            float4 a0 = *(const float4*)&As[kk][ty * 8];
            float4 a1 = *(const float4*)&As[kk][ty * 8 + 4];
            float4 b0 = *(const float4*)&Bs[kk][tx * 8];
            float4 b1 = *(const float4*)&Bs[kk][tx * 8 + 4];
            float a[8] = {a0.x, a0.y, a0.z, a0.w, a1.x, a1.y, a1.z, a1.w};
            float b[8] = {b0.x, b0.y, b0.z, b0.w, b1.x, b1.y, b1.z, b1.w};
            #pragma unroll
            for (int i = 0; i < 8; i++)
                #pragma unroll
                for (int j = 0; j < 8; j++)
                    acc[i][j] = fmaf(a[i], b[j], acc[i][j]);
        }
        __syncthreads();
    }

    #pragma unroll
    for (int i = 0; i < 8; i++) {
        float* Crow = C + (size_t)(m0 + ty * 8 + i) * N + n0 + tx * 8;
        float4 v0 = {acc[i][0], acc[i][1], acc[i][2], acc[i][3]};
        float4 v1 = {acc[i][4], acc[i][5], acc[i][6], acc[i][7]};
        *(float4*)(Crow)     = v0;
        *(float4*)(Crow + 4) = v1;
    }
}

// ---------------------------------------------------------------------------
// Flash attention (causal), fp32. One CTA = one (b, h, q-tile of 64 rows).
// 256 threads: ty=tid/16 (4 q-rows each), tx=tid%16 (4 cols each).
// Row reductions via 16-lane shuffle butterfly (tx == low 4 lane bits).
// Dynamic smem: Qs/Ks/Vs/Ps each 64x65 floats (stride 65 vs bank conflicts).
// ---------------------------------------------------------------------------
#define FSTRIDE 65
#define FTILE   (64 * FSTRIDE)

__global__ __launch_bounds__(256) void flash_attn_kernel(
    const float* __restrict__ qkv, float* __restrict__ outp)
{
    extern __shared__ float sm[];
    float* Qs = sm;
    float* Ks = sm + FTILE;
    float* Vs = sm + 2 * FTILE;
    float* Ps = sm + 3 * FTILE;

    const int tid = threadIdx.x;
    const int qt  = gridDim.x - 1 - blockIdx.x;   // heavy tiles first
    const int b   = blockIdx.y >> 4;
    const int h   = blockIdx.y & 15;
    const int q0  = qt * 64;

    const int ty = tid >> 4, tx = tid & 15;
    const int r0 = ty * 4,   c0 = tx * 4;

    const size_t rstride = 3 * Cc;
    const float scale = 0.125f;  // 1/sqrt(64)

    // ---- load Q tile (scaled) ----
    {
        const float* qbase = qkv + (size_t)(b * Tn + q0) * rstride + h * HD;
        #pragma unroll
        for (int it = 0; it < 4; it++) {
            int idx = tid + it * 256;
            int row = idx >> 4;
            int c4  = (idx & 15) << 2;
            float4 v = *(const float4*)(qbase + (size_t)row * rstride + c4);
            Qs[row * FSTRIDE + c4 + 0] = v.x * scale;
            Qs[row * FSTRIDE + c4 + 1] = v.y * scale;
            Qs[row * FSTRIDE + c4 + 2] = v.z * scale;
            Qs[row * FSTRIDE + c4 + 3] = v.w * scale;
        }
    }

    float mrow[4], lrow[4], o[4][4];
    #pragma unroll
    for (int i = 0; i < 4; i++) {
        mrow[i] = -1e30f; lrow[i] = 0.0f;
        #pragma unroll
        for (int j = 0; j < 4; j++) o[i][j] = 0.0f;
    }

    for (int kt = 0; kt <= qt; kt++) {
        const int k0 = kt * 64;
        // ---- load K, V tiles ----
        {
            const float* kbase = qkv + (size_t)(b * Tn + k0) * rstride + Cc + h * HD;
            const float* vbase = qkv + (size_t)(b * Tn + k0) * rstride + 2 * Cc + h * HD;
            #pragma unroll
            for (int it = 0; it < 4; it++) {
                int idx = tid + it * 256;
                int row = idx >> 4;
                int c4  = (idx & 15) << 2;
                float4 kv = *(const float4*)(kbase + (size_t)row * rstride + c4);
                float4 vv = *(const float4*)(vbase + (size_t)row * rstride + c4);
                Ks[row * FSTRIDE + c4 + 0] = kv.x; Ks[row * FSTRIDE + c4 + 1] = kv.y;
                Ks[row * FSTRIDE + c4 + 2] = kv.z; Ks[row * FSTRIDE + c4 + 3] = kv.w;
                Vs[row * FSTRIDE + c4 + 0] = vv.x; Vs[row * FSTRIDE + c4 + 1] = vv.y;
                Vs[row * FSTRIDE + c4 + 2] = vv.z; Vs[row * FSTRIDE + c4 + 3] = vv.w;
            }
        }
        __syncthreads();

        // ---- S = Q K^T (4x4 per thread) ----
        float s[4][4];
        #pragma unroll
        for (int i = 0; i < 4; i++)
            #pragma unroll
            for (int j = 0; j < 4; j++) s[i][j] = 0.0f;

        #pragma unroll 8
        for (int kk = 0; kk < 64; kk++) {
            float qf[4], kf[4];
            #pragma unroll
            for (int i = 0; i < 4; i++) qf[i] = Qs[(r0 + i) * FSTRIDE + kk];
            #pragma unroll
            for (int j = 0; j < 4; j++) kf[j] = Ks[(c0 + j) * FSTRIDE + kk];
            #pragma unroll
            for (int i = 0; i < 4; i++)
                #pragma unroll
                for (int j = 0; j < 4; j++)
                    s[i][j] = fmaf(qf[i], kf[j], s[i][j]);
        }

        // causal mask on diagonal tile
        if (kt == qt) {
            #pragma unroll
            for (int i = 0; i < 4; i++)
                #pragma unroll
                for (int j = 0; j < 4; j++)
                    if (c0 + j > r0 + i) s[i][j] = -1e30f;
        }

        // ---- online softmax ----
        #pragma unroll
        for (int i = 0; i < 4; i++) {
            float mx = fmaxf(fmaxf(s[i][0], s[i][1]), fmaxf(s[i][2], s[i][3]));
            #pragma unroll
            for (int off = 1; off < 16; off <<= 1)
                mx = fmaxf(mx, __shfl_xor_sync(0xffffffffu, mx, off));
            float nm = fmaxf(mrow[i], mx);
            float alpha = __expf(mrow[i] - nm);
            mrow[i] = nm;
            float rs = 0.0f;
            #pragma unroll
            for (int j = 0; j < 4; j++) {
                s[i][j] = __expf(s[i][j] - nm);
                rs += s[i][j];
            }
            #pragma unroll
            for (int off = 1; off < 16; off <<= 1)
                rs += __shfl_xor_sync(0xffffffffu, rs, off);
            lrow[i] = lrow[i] * alpha + rs;
            #pragma unroll
            for (int j = 0; j < 4; j++) {
                o[i][j] *= alpha;
                Ps[(r0 + i) * FSTRIDE + c0 + j] = s[i][j];
            }
        }
        __syncthreads();

        // ---- O += P @ V ----
        #pragma unroll 8
        for (int kk = 0; kk < 64; kk++) {
            float pf[4], vf[4];
            #pragma unroll
            for (int i = 0; i < 4; i++) pf[i] = Ps[(r0 + i) * FSTRIDE + kk];
            #pragma unroll
            for (int j = 0; j < 4; j++) vf[j] = Vs[kk * FSTRIDE + c0 + j];
            #pragma unroll
            for (int i = 0; i < 4; i++)
                #pragma unroll
                for (int j = 0; j < 4; j++)
                    o[i][j] = fmaf(pf[i], vf[j], o[i][j]);
        }
        __syncthreads();   // protect Ks/Vs/Ps before next iteration's loads
    }

    // ---- normalize + write (layout (B,T,C): heads interleaved back) ----
    float* obase = outp + (size_t)(b * Tn + q0) * Cc + h * HD;
    #pragma unroll
    for (int i = 0; i < 4; i++) {
        float inv = 1.0f / lrow[i];
        float4 v = {o[i][0] * inv, o[i][1] * inv, o[i][2] * inv, o[i][3] * inv};
        *(float4*)(obase + (size_t)(r0 + i) * Cc + c0) = v;
    }
}

// ---------------------------------------------------------------------------
// Launch
// ---------------------------------------------------------------------------
extern "C" void kernel_launch(void* const* d_in, const int* in_sizes, int n_in,
                              void* d_out, int out_size)
{
    const float* x      = (const float*)d_in[0];   // (B,T,C)
    const float* w_attn = (const float*)d_in[1];   // (3C, C)
    const float* w_proj = (const float*)d_in[2];   // (C, C)
    float* out = (float*)d_out;                    // (B,T,C)

    float* qkv_p = nullptr;
    float* att_p = nullptr;
    cudaGetSymbolAddress((void**)&qkv_p, g_qkv);
    cudaGetSymbolAddress((void**)&att_p, g_att);

    // 1) QKV = x @ w_attn^T : M=8192, N=3072, K=1024
    {
        dim3 grid(3 * Cc / 128, MTOT / 128);
        gemm_nt_kernel<<<grid, 256>>>(x, w_attn, qkv_p, MTOT, 3 * Cc, Cc);
    }

    // 2) Flash attention
    {
        const int smem = 4 * FTILE * sizeof(float);   // 66560 B
        cudaFuncSetAttribute(flash_attn_kernel,
                             cudaFuncAttributeMaxDynamicSharedMemorySize, smem);
        dim3 grid(Tn / 64, Bn * NH);
        flash_attn_kernel<<<grid, 256, smem>>>(qkv_p, att_p);
    }

    // 3) out = att @ w_proj^T : M=8192, N=1024, K=1024
    {
        dim3 grid(Cc / 128, MTOT / 128);
        gemm_nt_kernel<<<grid, 256>>>(att_p, w_proj, out, MTOT, Cc, Cc);
    }
}

// round 5
// speedup vs baseline: 3.5327x; 3.5327x over previous
#include <cuda_runtime.h>
#include <math.h>
#include <stdint.h>

// Problem constants (B=4, T=2048, C=1024, H=16, D=64)
#define Bn   4
#define Tn   2048
#define Cc   1024
#define NH   16
#define HD   64
#define MTOT (Bn * Tn)          // 8192 rows

// Scratch (device globals: allocation is forbidden)
__device__ float g_qkv[(size_t)MTOT * 3 * Cc];  // (B*T, 3C)
__device__ float g_att[(size_t)MTOT * Cc];      // (B*T, C)

// ===========================================================================
// Helpers (sm_80+ PTX only — this toolchain targets sm_103 WITHOUT the 'a'
// suffix, so tcgen05/TMEM are unavailable; mma.sync is the tensor path)
// ===========================================================================
__device__ __forceinline__ uint32_t smem_u32(const void* p) {
    uint32_t a;
    asm("{ .reg .u64 t; cvta.to.shared.u64 t, %1; cvt.u32.u64 %0, t; }"
        : "=r"(a) : "l"(p));
    return a;
}
// f32 -> tf32 (round-to-nearest; truncation would bias long dots by ~5e-4)
__device__ __forceinline__ uint32_t f2tf32(float x) {
    uint32_t y;
    asm("cvt.rna.tf32.f32 %0, %1;" : "=r"(y) : "f"(x));
    return y;
}
__device__ __forceinline__ uint32_t lds_tf32(const float* p) {
    float v = *p;
    uint32_t y;
    asm("cvt.rna.tf32.f32 %0, %1;" : "=r"(y) : "f"(v));
    return y;
}
// D = A@B + D, m16n8k8 tf32
__device__ __forceinline__ void mma_tf32(float* c, const uint32_t* a, const uint32_t* b) {
    asm volatile(
        "mma.sync.aligned.m16n8k8.row.col.f32.tf32.tf32.f32 "
        "{%0,%1,%2,%3}, {%4,%5,%6,%7}, {%8,%9}, {%0,%1,%2,%3};"
        : "+f"(c[0]), "+f"(c[1]), "+f"(c[2]), "+f"(c[3])
        : "r"(a[0]), "r"(a[1]), "r"(a[2]), "r"(a[3]), "r"(b[0]), "r"(b[1]));
}
#define CP16(smem, gmem) \
    asm volatile("cp.async.cg.shared.global [%0], [%1], 16;" \
                 :: "r"(smem), "l"(gmem) : "memory")
#define CP_COMMIT() asm volatile("cp.async.commit_group;" ::: "memory")
#define CP_WAIT0()  asm volatile("cp.async.wait_group 0;" ::: "memory")
#define CP_WAIT1()  asm volatile("cp.async.wait_group 1;" ::: "memory")

// ===========================================================================
// TF32 tensor-core GEMM: C[M,N] = A[M,K] @ B[N,K]^T  (row-major, all %128==0)
// 128x128 CTA tile, BK=32, 256 threads (8 warps, 2x4 warp grid, 64x32/warp).
// cp.async double buffer; fragments via LDS + cvt.rna.tf32.
// Smem stride 36 floats: fragment gather bank = (4r+c) mod 32 -> conflict-free.
// ===========================================================================
#define GA_ST   36
#define GTILE   (128 * GA_ST)                 // floats per A (or B) tile
#define GEMM_SMEM (2 * 2 * GTILE * 4)         // 73728 B

__global__ __launch_bounds__(256) void gemm_tc_kernel(
    const float* __restrict__ A, const float* __restrict__ B,
    float* __restrict__ C, int N, int K)
{
    extern __shared__ float sg[];
    const uint32_t sb = smem_u32(sg);
    const int tid = threadIdx.x;
    const int wid = tid >> 5, lane = tid & 31;
    const int gr = lane >> 2, gc = lane & 3;
    const int m0 = blockIdx.y * 128, n0 = blockIdx.x * 128;
    const int wm0 = (wid >> 2) * 64, wn0 = (wid & 3) * 32;

    float acc[4][4][4];
    #pragma unroll
    for (int i = 0; i < 4; i++)
        #pragma unroll
        for (int j = 0; j < 4; j++)
            #pragma unroll
            for (int r = 0; r < 4; r++) acc[i][j][r] = 0.0f;

    // global->smem geometry: 4 rows per thread per tile (rows r0+32*it)
    const int r0 = tid >> 3;
    const int c4 = (tid & 7) * 4;
    const float* Ag = A + (size_t)(m0 + r0) * K + c4;
    const float* Bg = B + (size_t)(n0 + r0) * K + c4;

    const int KCH = K / 32;
    int buf = 0;

    // prefetch chunk 0
    #pragma unroll
    for (int it = 0; it < 4; it++) {
        uint32_t so = sb + (uint32_t)(((r0 + it * 32) * GA_ST + c4) * 4);
        CP16(so,             Ag + (size_t)it * 32 * K);
        CP16(so + GTILE * 4, Bg + (size_t)it * 32 * K);
    }
    CP_COMMIT();

    for (int c = 0; c < KCH; c++) {
        if (c + 1 < KCH) {
            const int nb = buf ^ 1;
            #pragma unroll
            for (int it = 0; it < 4; it++) {
                uint32_t so = sb + (uint32_t)((nb * 2 * GTILE +
                                (r0 + it * 32) * GA_ST + c4) * 4);
                CP16(so,             Ag + (size_t)it * 32 * K + (c + 1) * 32);
                CP16(so + GTILE * 4, Bg + (size_t)it * 32 * K + (c + 1) * 32);
            }
            CP_COMMIT();
            CP_WAIT1();
        } else {
            CP_WAIT0();
        }
        __syncthreads();

        const float* As = sg + buf * 2 * GTILE;
        const float* Bs = As + GTILE;
        #pragma unroll
        for (int ks = 0; ks < 4; ks++) {
            uint32_t af[4][4], bf[4][2];
            #pragma unroll
            for (int i = 0; i < 4; i++) {
                const float* ap = As + (wm0 + i * 16 + gr) * GA_ST + ks * 8 + gc;
                af[i][0] = lds_tf32(ap);
                af[i][1] = lds_tf32(ap + 8 * GA_ST);
                af[i][2] = lds_tf32(ap + 4);
                af[i][3] = lds_tf32(ap + 8 * GA_ST + 4);
            }
            #pragma unroll
            for (int j = 0; j < 4; j++) {
                const float* bp = Bs + (wn0 + j * 8 + gr) * GA_ST + ks * 8 + gc;
                bf[j][0] = lds_tf32(bp);
                bf[j][1] = lds_tf32(bp + 4);
            }
            #pragma unroll
            for (int i = 0; i < 4; i++)
                #pragma unroll
                for (int j = 0; j < 4; j++)
                    mma_tf32(acc[i][j], af[i], bf[j]);
        }
        __syncthreads();
        buf ^= 1;
    }

    // epilogue: c0,c1 -> (row, 2gc..2gc+1); c2,c3 -> row+8
    #pragma unroll
    for (int i = 0; i < 4; i++)
        #pragma unroll
        for (int j = 0; j < 4; j++) {
            float* cr = C + (size_t)(m0 + wm0 + i * 16 + gr) * N
                          + n0 + wn0 + j * 8 + gc * 2;
            float2 v0 = { acc[i][j][0], acc[i][j][1] };
            float2 v1 = { acc[i][j][2], acc[i][j][3] };
            *(float2*)cr           = v0;
            *(float2*)(cr + 8 * N) = v1;
        }
}

// ===========================================================================
// Flash attention (causal) on mma.sync tf32.
// CTA: 128 threads (4 warps), q-tile 64 (warp owns 16 q rows), D=64.
// Q lives in registers as tf32 A-fragments. K/V double-buffered via cp.async.
// S accums reused as P (through smem for the C->A layout fixup).
// Strides: K/P 68 (8rx4c gather conflict-free), V 72 (4rx8c gather).
// ===========================================================================
#define KST 68
#define VST 72
#define PST 68
#define FLASH_SMEM ((2 * 64 * KST + 2 * 64 * VST + 64 * PST) * 4)  // 89088 B

__global__ __launch_bounds__(128) void flash_tc_kernel(
    const float* __restrict__ qkv, float* __restrict__ outp)
{
    extern __shared__ float sf[];
    float* Ksm = sf;                        // [2][64*KST]
    float* Vsm = sf + 2 * 64 * KST;         // [2][64*VST]
    float* Psm = Vsm + 2 * 64 * VST;        // [64*PST]
    const uint32_t sb = smem_u32(sf);

    const int tid = threadIdx.x;
    const int wid = tid >> 5, lane = tid & 31;
    const int gr = lane >> 2, gc = lane & 3;
    const int qt = gridDim.x - 1 - blockIdx.x;      // heavy tiles first
    const int b  = blockIdx.y >> 4;
    const int h  = blockIdx.y & 15;
    const int q0 = qt * 64;
    const int wq0 = wid * 16;
    const size_t rst = 3 * Cc;

    // ---- Q fragments in registers (scaled + tf32) ----
    uint32_t qf[8][4];
    {
        const float* qb = qkv + (size_t)(b * Tn + q0 + wq0) * rst + h * HD;
        const float* qlo = qb + (size_t)gr * rst;
        const float* qhi = qlo + 8 * rst;
        #pragma unroll
        for (int ks = 0; ks < 8; ks++) {
            qf[ks][0] = f2tf32(qlo[ks * 8 + gc]     * 0.125f);
            qf[ks][1] = f2tf32(qhi[ks * 8 + gc]     * 0.125f);
            qf[ks][2] = f2tf32(qlo[ks * 8 + gc + 4] * 0.125f);
            qf[ks][3] = f2tf32(qhi[ks * 8 + gc + 4] * 0.125f);
        }
    }

    float o[8][4];
    #pragma unroll
    for (int j = 0; j < 8; j++)
        #pragma unroll
        for (int r = 0; r < 4; r++) o[j][r] = 0.0f;
    float m_lo = -1e30f, m_hi = -1e30f, l_lo = 0.0f, l_hi = 0.0f;

    // K/V gmem->smem geometry: 8 rows per thread (rows r0+8*it), 16B each
    const int r0 = tid >> 4;
    const int c4 = (tid & 15) * 4;
    const float* kb0 = qkv + (size_t)(b * Tn) * rst + Cc + h * HD;

    // prefetch kt=0
    {
        const float* kb = kb0;
        #pragma unroll
        for (int it = 0; it < 8; it++) {
            const int row = r0 + it * 8;
            uint32_t ko = sb + (uint32_t)((row * KST + c4) * 4);
            uint32_t vo = sb + (uint32_t)((2 * 64 * KST + row * VST + c4) * 4);
            CP16(ko, kb + (size_t)row * rst + c4);
            CP16(vo, kb + (size_t)row * rst + Cc + c4);
        }
        CP_COMMIT();
    }

    int buf = 0;
    for (int kt = 0; kt <= qt; kt++) {
        if (kt < qt) {
            const int nb = buf ^ 1;
            const float* kb = kb0 + (size_t)(kt + 1) * 64 * rst;
            #pragma unroll
            for (int it = 0; it < 8; it++) {
                const int row = r0 + it * 8;
                uint32_t ko = sb + (uint32_t)((nb * 64 * KST + row * KST + c4) * 4);
                uint32_t vo = sb + (uint32_t)((2 * 64 * KST + nb * 64 * VST +
                                               row * VST + c4) * 4);
                CP16(ko, kb + (size_t)row * rst + c4);
                CP16(vo, kb + (size_t)row * rst + Cc + c4);
            }
            CP_COMMIT();
            CP_WAIT1();
        } else {
            CP_WAIT0();
        }
        __syncthreads();

        const float* Ks = Ksm + buf * 64 * KST;
        const float* Vs = Vsm + buf * 64 * VST;

        // ---- S = Q @ K^T ----
        float s[8][4];
        #pragma unroll
        for (int j = 0; j < 8; j++)
            #pragma unroll
            for (int r = 0; r < 4; r++) s[j][r] = 0.0f;

        #pragma unroll
        for (int ks = 0; ks < 8; ks++) {
            #pragma unroll
            for (int j = 0; j < 8; j++) {
                uint32_t bf[2];
                const float* kp = Ks + (j * 8 + gr) * KST + ks * 8 + gc;
                bf[0] = lds_tf32(kp);
                bf[1] = lds_tf32(kp + 4);
                mma_tf32(s[j], qf[ks], bf);
            }
        }

        // ---- causal mask on diagonal tile ----
        if (kt == qt) {
            const int qlo = wq0 + gr, qhi = qlo + 8;
            #pragma unroll
            for (int j = 0; j < 8; j++) {
                const int col = j * 8 + gc * 2;
                if (col     > qlo) s[j][0] = -1e30f;
                if (col + 1 > qlo) s[j][1] = -1e30f;
                if (col     > qhi) s[j][2] = -1e30f;
                if (col + 1 > qhi) s[j][3] = -1e30f;
            }
        }

        // ---- online softmax (rows lo = lane>>2, hi = +8) ----
        {
            float mx_lo = -1e30f, mx_hi = -1e30f;
            #pragma unroll
            for (int j = 0; j < 8; j++) {
                mx_lo = fmaxf(mx_lo, fmaxf(s[j][0], s[j][1]));
                mx_hi = fmaxf(mx_hi, fmaxf(s[j][2], s[j][3]));
            }
            mx_lo = fmaxf(mx_lo, __shfl_xor_sync(0xffffffffu, mx_lo, 1));
            mx_lo = fmaxf(mx_lo, __shfl_xor_sync(0xffffffffu, mx_lo, 2));
            mx_hi = fmaxf(mx_hi, __shfl_xor_sync(0xffffffffu, mx_hi, 1));
            mx_hi = fmaxf(mx_hi, __shfl_xor_sync(0xffffffffu, mx_hi, 2));

            const float nm_lo = fmaxf(m_lo, mx_lo);
            const float nm_hi = fmaxf(m_hi, mx_hi);
            const float al_lo = __expf(m_lo - nm_lo);
            const float al_hi = __expf(m_hi - nm_hi);
            m_lo = nm_lo; m_hi = nm_hi;

            float sm_lo = 0.0f, sm_hi = 0.0f;
            #pragma unroll
            for (int j = 0; j < 8; j++) {
                s[j][0] = __expf(s[j][0] - nm_lo);
                s[j][1] = __expf(s[j][1] - nm_lo);
                s[j][2] = __expf(s[j][2] - nm_hi);
                s[j][3] = __expf(s[j][3] - nm_hi);
                sm_lo += s[j][0] + s[j][1];
                sm_hi += s[j][2] + s[j][3];
            }
            sm_lo += __shfl_xor_sync(0xffffffffu, sm_lo, 1);
            sm_lo += __shfl_xor_sync(0xffffffffu, sm_lo, 2);
            sm_hi += __shfl_xor_sync(0xffffffffu, sm_hi, 1);
            sm_hi += __shfl_xor_sync(0xffffffffu, sm_hi, 2);
            l_lo = l_lo * al_lo + sm_lo;
            l_hi = l_hi * al_hi + sm_hi;

            #pragma unroll
            for (int j = 0; j < 8; j++) {
                o[j][0] *= al_lo; o[j][1] *= al_lo;
                o[j][2] *= al_hi; o[j][3] *= al_hi;
            }
        }

        // ---- store P (tf32 bits) to warp-private Ps rows ----
        {
            uint32_t* pp = (uint32_t*)Psm + (wq0 + gr) * PST + gc * 2;
            #pragma unroll
            for (int j = 0; j < 8; j++) {
                pp[j * 8]               = f2tf32(s[j][0]);
                pp[j * 8 + 1]           = f2tf32(s[j][1]);
                pp[j * 8 + 8 * PST]     = f2tf32(s[j][2]);
                pp[j * 8 + 8 * PST + 1] = f2tf32(s[j][3]);
            }
        }
        __syncwarp();

        // ---- O += P @ V ----
        #pragma unroll
        for (int kk = 0; kk < 8; kk++) {
            uint32_t pf[4];
            const uint32_t* pq = (const uint32_t*)Psm + (wq0 + gr) * PST + kk * 8 + gc;
            pf[0] = pq[0];
            pf[1] = pq[8 * PST];
            pf[2] = pq[4];
            pf[3] = pq[8 * PST + 4];
            #pragma unroll
            for (int j2 = 0; j2 < 8; j2++) {
                uint32_t vf[2];
                const float* vp = Vs + (kk * 8 + gc) * VST + j2 * 8 + gr;
                vf[0] = lds_tf32(vp);
                vf[1] = lds_tf32(vp + 4 * VST);
                mma_tf32(o[j2], pf, vf);
            }
        }
        __syncwarp();           // Ps reads done before next iteration's writes
        __syncthreads();        // K/V buffer reads done before overwrite
        buf ^= 1;
    }

    // ---- normalize + write ----
    {
        const float il_lo = 1.0f / l_lo;
        const float il_hi = 1.0f / l_hi;
        float* ob = outp + (size_t)(b * Tn + q0 + wq0) * Cc + h * HD;
        float* olo = ob + (size_t)gr * Cc + gc * 2;
        float* ohi = olo + (size_t)8 * Cc;
        #pragma unroll
        for (int j2 = 0; j2 < 8; j2++) {
            float2 v0 = { o[j2][0] * il_lo, o[j2][1] * il_lo };
            float2 v1 = { o[j2][2] * il_hi, o[j2][3] * il_hi };
            *(float2*)(olo + j2 * 8) = v0;
            *(float2*)(ohi + j2 * 8) = v1;
        }
    }
}

// ===========================================================================
// Launch
// ===========================================================================
extern "C" void kernel_launch(void* const* d_in, const int* in_sizes, int n_in,
                              void* d_out, int out_size)
{
    const float* x      = (const float*)d_in[0];   // (B,T,C)
    const float* w_attn = (const float*)d_in[1];   // (3C, C)
    const float* w_proj = (const float*)d_in[2];   // (C, C)
    float* out = (float*)d_out;                    // (B,T,C)

    float* qkv_p = nullptr;
    float* att_p = nullptr;
    cudaGetSymbolAddress((void**)&qkv_p, g_qkv);
    cudaGetSymbolAddress((void**)&att_p, g_att);

    cudaFuncSetAttribute(gemm_tc_kernel,
                         cudaFuncAttributeMaxDynamicSharedMemorySize, GEMM_SMEM);
    cudaFuncSetAttribute(flash_tc_kernel,
                         cudaFuncAttributeMaxDynamicSharedMemorySize, FLASH_SMEM);

    // 1) QKV = x @ w_attn^T : M=8192, N=3072, K=1024
    {
        dim3 grid(3 * Cc / 128, MTOT / 128);
        gemm_tc_kernel<<<grid, 256, GEMM_SMEM>>>(x, w_attn, qkv_p, 3 * Cc, Cc);
    }

    // 2) Flash attention (tf32 mma)
    {
        dim3 grid(Tn / 64, Bn * NH);
        flash_tc_kernel<<<grid, 128, FLASH_SMEM>>>(qkv_p, att_p);
    }

    // 3) out = att @ w_proj^T : M=8192, N=1024, K=1024
    {
        dim3 grid(Cc / 128, MTOT / 128);
        gemm_tc_kernel<<<grid, 256, GEMM_SMEM>>>(att_p, w_proj, out, Cc, Cc);
    }
}